// round 5
// baseline (speedup 1.0000x reference)
#include <cuda_runtime.h>
#include <cstdint>

// GraphAttentionPooling: B=32, N=3072, F=256, P=3 -> 32768 windows of 3x256.
// Persistent 148 blocks x 256 threads. Each block grid-strides over tiles of
// 8 windows (24 KB contiguous). TMA bulk-copy (cp.async.bulk + mbarrier)
// 6-stage smem pipeline decouples in-flight DRAM bytes from registers.
// Consumer: warp w handles window w of the tile from smem.

#define S_STAGES     6
#define TILE_WINDOWS 8
#define WIN_FLOATS   768          // 3 rows * 256
#define WIN_BYTES    3072
#define TILE_BYTES   (TILE_WINDOWS * WIN_BYTES)   // 24576
#define THREADS      256
#define NUM_SMS      148
#define SMEM_DATA_OFF 1024
#define SMEM_TOTAL   (SMEM_DATA_OFF + S_STAGES * TILE_BYTES)  // 148480

__device__ __forceinline__ uint32_t smem_u32(const void* p) {
    uint32_t a;
    asm("{ .reg .u64 t; cvta.to.shared.u64 t, %1; cvt.u32.u64 %0, t; }"
        : "=r"(a) : "l"(p));
    return a;
}

#define MBAR_INIT(addr, cnt) \
    asm volatile("mbarrier.init.shared.b64 [%0], %1;" :: "r"(addr), "r"(cnt) : "memory")
#define MBAR_EXPECT_TX(addr, bytes) \
    asm volatile("mbarrier.arrive.expect_tx.shared.b64 _, [%0], %1;" :: "r"(addr), "r"(bytes) : "memory")
#define MBAR_ARRIVE(addr) \
    asm volatile("mbarrier.arrive.shared.b64 _, [%0];" :: "r"(addr) : "memory")
#define TMA_BULK_G2S(dst, src, bytes, mbar) \
    asm volatile("cp.async.bulk.shared::cta.global.mbarrier::complete_tx::bytes [%0], [%1], %2, [%3];" \
                 :: "r"(dst), "l"(src), "r"(bytes), "r"(mbar) : "memory")

__device__ __forceinline__ void mbar_wait(uint32_t mbar, uint32_t parity) {
    asm volatile(
        "{\n\t"
        ".reg .pred P;\n\t"
        "WAIT_%=: mbarrier.try_wait.parity.acquire.cta.shared::cta.b64 P, [%0], %1, 0x989680;\n\t"
        "@P bra.uni DONE_%=;\n\t"
        "bra.uni WAIT_%=;\n\t"
        "DONE_%=:\n\t"
        "}"
        :: "r"(mbar), "r"(parity) : "memory");
}

__device__ __forceinline__ float warp_reduce_sum(float v) {
    #pragma unroll
    for (int off = 16; off > 0; off >>= 1)
        v += __shfl_xor_sync(0xFFFFFFFFu, v, off);
    return v;
}

__device__ __forceinline__ float dot8(float4 a, float4 b, float4 wa, float4 wb) {
    float s = a.x * wa.x;
    s = fmaf(a.y, wa.y, s);
    s = fmaf(a.z, wa.z, s);
    s = fmaf(a.w, wa.w, s);
    s = fmaf(b.x, wb.x, s);
    s = fmaf(b.y, wb.y, s);
    s = fmaf(b.z, wb.z, s);
    s = fmaf(b.w, wb.w, s);
    return s;
}

__global__ void __launch_bounds__(THREADS, 1)
gap_kernel(const float* __restrict__ x,
           const float* __restrict__ Ww,
           const float* __restrict__ Wb,
           float* __restrict__ out,
           int n_tiles) {
    extern __shared__ char smem[];
    const uint32_t sbase = smem_u32(smem);
    const int tid  = threadIdx.x;
    const int warp = tid >> 5;
    const int lane = tid & 31;

    // Barriers: full[s] at sbase + s*16, empty[s] at sbase + s*16 + 8.
    if (tid == 0) {
        #pragma unroll
        for (int s = 0; s < S_STAGES; s++) {
            MBAR_INIT(sbase + s * 16,     1);            // full: 1 arrive (expect_tx)
            MBAR_INIT(sbase + s * 16 + 8, TILE_WINDOWS); // empty: 8 warp arrivals
        }
    }
    __syncthreads();

    // Weights: lane l owns features [4l,4l+4) and [128+4l,128+4l+4).
    const float4* Wv = reinterpret_cast<const float4*>(Ww);
    const float4 wa = Wv[lane], wb = Wv[lane + 32];
    const float bias = Wb[0];

    const int bid  = blockIdx.x;
    const int grid = gridDim.x;

    // Producer prologue: fill stages 0..S-2 (round 0, slots initially free).
    if (tid == 0) {
        #pragma unroll
        for (int jj = 0; jj < S_STAGES - 1; jj++) {
            int g = bid + jj * grid;
            if (g < n_tiles) {
                uint32_t fullb = sbase + jj * 16;
                MBAR_EXPECT_TX(fullb, TILE_BYTES);
                const char* src = (const char*)x + (size_t)g * TILE_BYTES;
                TMA_BULK_G2S(sbase + SMEM_DATA_OFF + jj * TILE_BYTES, src,
                             TILE_BYTES, fullb);
            }
        }
    }

    for (int j = 0; ; j++) {
        const int g = bid + j * grid;
        if (g >= n_tiles) break;
        const int slot  = j % S_STAGES;
        const int round = j / S_STAGES;

        // Producer: issue tile jj = j + S-1 into its slot (after empty-wait on reuse).
        if (tid == 0) {
            int jj = j + S_STAGES - 1;
            int gg = bid + jj * grid;
            if (gg < n_tiles) {
                int ps = jj % S_STAGES;
                int k  = jj / S_STAGES;
                uint32_t fullb  = sbase + ps * 16;
                uint32_t emptyb = sbase + ps * 16 + 8;
                if (k > 0) mbar_wait(emptyb, (uint32_t)((k - 1) & 1));
                MBAR_EXPECT_TX(fullb, TILE_BYTES);
                const char* src = (const char*)x + (size_t)gg * TILE_BYTES;
                TMA_BULK_G2S(sbase + SMEM_DATA_OFF + ps * TILE_BYTES, src,
                             TILE_BYTES, fullb);
            }
        }

        // Consumer: wait for this tile's data.
        mbar_wait(sbase + slot * 16, (uint32_t)(round & 1));

        // Warp w processes window w of the tile.
        const float4* w4 = reinterpret_cast<const float4*>(
            smem + SMEM_DATA_OFF + slot * TILE_BYTES + warp * WIN_BYTES);
        // Conflict-free LDS.128: lane l reads float4 idx (32*chunk + l).
        float4 r0a = w4[lane],       r0b = w4[lane + 32];
        float4 r1a = w4[lane + 64],  r1b = w4[lane + 96];
        float4 r2a = w4[lane + 128], r2b = w4[lane + 160];

        float s0 = warp_reduce_sum(dot8(r0a, r0b, wa, wb)) + bias;
        float s1 = warp_reduce_sum(dot8(r1a, r1b, wa, wb)) + bias;
        float s2 = warp_reduce_sum(dot8(r2a, r2b, wa, wb)) + bias;

        float m = fmaxf(s0, fmaxf(s1, s2));
        float e0 = __expf(s0 - m);
        float e1 = __expf(s1 - m);
        float e2 = __expf(s2 - m);
        float inv = 1.0f / (e0 + e1 + e2);
        float a0 = e0 * inv, a1 = e1 * inv, a2 = e2 * inv;

        float4 oa, ob;
        oa.x = fmaf(r2a.x, a2, fmaf(r1a.x, a1, r0a.x * a0));
        oa.y = fmaf(r2a.y, a2, fmaf(r1a.y, a1, r0a.y * a0));
        oa.z = fmaf(r2a.z, a2, fmaf(r1a.z, a1, r0a.z * a0));
        oa.w = fmaf(r2a.w, a2, fmaf(r1a.w, a1, r0a.w * a0));
        ob.x = fmaf(r2b.x, a2, fmaf(r1b.x, a1, r0b.x * a0));
        ob.y = fmaf(r2b.y, a2, fmaf(r1b.y, a1, r0b.y * a0));
        ob.z = fmaf(r2b.z, a2, fmaf(r1b.z, a1, r0b.z * a0));
        ob.w = fmaf(r2b.w, a2, fmaf(r1b.w, a1, r0b.w * a0));

        float4* o4 = reinterpret_cast<float4*>(
            out + ((size_t)g * TILE_WINDOWS + warp) * 256);
        __stcs(o4 + lane,      oa);
        __stcs(o4 + lane + 32, ob);

        // Release the slot (one arrival per warp; reads already consumed).
        if (lane == 0) MBAR_ARRIVE(sbase + slot * 16 + 8);
    }
}

extern "C" void kernel_launch(void* const* d_in, const int* in_sizes, int n_in,
                              void* d_out, int out_size) {
    const float* x  = (const float*)d_in[0];  // [32, 3072, 256]
    const float* Ww = (const float*)d_in[1];  // [256]
    const float* Wb = (const float*)d_in[2];  // [1]
    float* out = (float*)d_out;               // [32, 1024, 256, 1]

    const int n_windows = in_sizes[0] / WIN_FLOATS;      // 32768
    const int n_tiles   = n_windows / TILE_WINDOWS;      // 4096

    cudaFuncSetAttribute(gap_kernel,
                         cudaFuncAttributeMaxDynamicSharedMemorySize, SMEM_TOTAL);

    gap_kernel<<<NUM_SMS, THREADS, SMEM_TOTAL>>>(x, Ww, Wb, out, n_tiles);
}